// round 2
// baseline (speedup 1.0000x reference)
#include <cuda_runtime.h>
#include <cstdint>

// ---------------------------------------------------------------------------
// LSTMPredictor: 2-layer LSTM (H=512) over T=512 steps, B=256, IN=64, OUT=64.
// Persistent-kernel design: 132 co-resident CTAs, grid barrier between the two
// recurrent GEMM phases of each timestep. TF32 mma.sync with fp32 accumulate.
//
// Phase A (per step t): gates0 = [x_t | h0_old] @ [W_ih0 | W_hh0]^T  (K=576)
//                       -> LSTM cell -> h0_new, c0   (fused epilogue)
//          + 4 CTAs compute the output linear for step t-1 in parallel.
// Phase B:              gates1 = [h0_new | h1_old] @ [W_ih1 | W_hh1]^T (K=1024)
//                       -> LSTM cell -> h1_new, c1
//
// Tiling: gemm tiles are 64 rows (batch) x 64 gate-cols, where the 64 columns
// are 4 groups of 16 matching columns from gates i,f,g,o -> the cell is local
// to the CTA. 128 gemm tiles (4 M x 32 column-groups) + 4 linear tiles = 132.
// ---------------------------------------------------------------------------

namespace {
constexpr int T_STEPS = 512;
constexpr int BATCH   = 256;
constexpr int IN_DIM  = 64;
constexpr int HID     = 512;
constexpr int OUT_DIM = 64;
constexpr int NCTA    = 132;
}

// Persistent state (static device scratch; allocation-free).
__device__ float g_h0[2][BATCH * HID];
__device__ float g_h1[2][BATCH * HID];
__device__ float g_c0[BATCH * HID];
__device__ float g_c1[BATCH * HID];
__device__ unsigned g_count;
__device__ unsigned g_gen;

__device__ __forceinline__ float rtf32(float v) {
    asm("cvt.rna.tf32.f32 %0, %1;" : "=f"(v) : "f"(v));
    return v;
}

__device__ __forceinline__ float sigf(float v) {
    return 1.0f / (1.0f + __expf(-v));
}

__device__ __forceinline__ void mma_tf32(float (&d)[4], const uint32_t (&a)[4],
                                         const uint32_t (&b)[2]) {
    asm volatile(
        "mma.sync.aligned.m16n8k8.row.col.f32.tf32.tf32.f32 "
        "{%0,%1,%2,%3},{%4,%5,%6,%7},{%8,%9},{%0,%1,%2,%3};"
        : "+f"(d[0]), "+f"(d[1]), "+f"(d[2]), "+f"(d[3])
        : "r"(a[0]), "r"(a[1]), "r"(a[2]), "r"(a[3]), "r"(b[0]), "r"(b[1]));
}

// Grid-wide sense-reversal barrier. All CTAs resident (132 <= 148 SMs).
__device__ __forceinline__ void grid_sync(unsigned &gen) {
    const unsigned target = gen + 1;
    __syncthreads();
    if (threadIdx.x == 0) {
        __threadfence();
        unsigned prev = atomicAdd(&g_count, 1u);
        if (prev == gridDim.x - 1) {
            g_count = 0;
            __threadfence();
            atomicExch(&g_gen, target);
        } else {
            const volatile unsigned* p = &g_gen;
            while (*p != target) {}
            __threadfence();
        }
    }
    __syncthreads();
    gen = target;
}

// ---------------------------------------------------------------------------
// Tiled GEMM: 64x64 output tile, K-blocked by 32, 4 warps (2x2 of 32x32),
// m16n8k8 tf32 mma. A = activations (K-major), B = weight rows (K-major).
// PH==0: A = [x_t | h0_old], B rows from W_ih0/W_hh0, K=576
// PH==1: A = [h0_new | h1_old], B rows from W_ih1/W_hh1, K=1024
// PH==2: A = h1, B rows = W_lin, K=512  (output linear)
// For PH 0/1, the tile's local column n_local maps to global gate row
//   n = (n_local/16)*512 + j0 + (n_local%16)   (4 gate groups of 16 columns)
// ---------------------------------------------------------------------------
template <int PH>
__device__ __forceinline__ void fetchAB(
    int kb, int m0, int j0,
    const float* __restrict__ A0, const float* __restrict__ A1,
    const float* __restrict__ B0, const float* __restrict__ B1,
    float4 (&ra)[4], float4 (&rb)[4]) {
    const int tid = threadIdx.x;
#pragma unroll
    for (int r = 0; r < 4; r++) {
        const int item = tid + 128 * r;
        const int row  = item >> 3;
        const int k    = kb + 4 * (item & 7);
        // A tile: recurrent state -> L2-coherent loads (.cg); x is immutable.
        if (PH == 0) {
            if (k < IN_DIM)
                ra[r] = *reinterpret_cast<const float4*>(A0 + (m0 + row) * IN_DIM + k);
            else
                ra[r] = __ldcg(reinterpret_cast<const float4*>(A1 + (m0 + row) * HID + (k - IN_DIM)));
        } else if (PH == 1) {
            if (k < HID)
                ra[r] = __ldcg(reinterpret_cast<const float4*>(A0 + (m0 + row) * HID + k));
            else
                ra[r] = __ldcg(reinterpret_cast<const float4*>(A1 + (m0 + row) * HID + (k - HID)));
        } else {
            ra[r] = __ldcg(reinterpret_cast<const float4*>(A0 + (m0 + row) * HID + k));
        }
        // B tile: weights (immutable inputs).
        if (PH == 2) {
            rb[r] = *reinterpret_cast<const float4*>(B0 + row * HID + k);
        } else {
            const int n = ((row >> 4) << 9) + j0 + (row & 15);
            if (PH == 0) {
                if (k < IN_DIM)
                    rb[r] = *reinterpret_cast<const float4*>(B0 + n * IN_DIM + k);
                else
                    rb[r] = *reinterpret_cast<const float4*>(B1 + n * HID + (k - IN_DIM));
            } else {
                if (k < HID)
                    rb[r] = *reinterpret_cast<const float4*>(B0 + n * HID + k);
                else
                    rb[r] = *reinterpret_cast<const float4*>(B1 + n * HID + (k - HID));
            }
        }
    }
}

template <int PH>
__device__ __forceinline__ void run_gemm(
    const float* __restrict__ A0, const float* __restrict__ A1,
    const float* __restrict__ B0, const float* __restrict__ B1,
    int m0, int j0, float* smem, float (&acc)[2][4][4]) {
    constexpr int KTOT = (PH == 0) ? (IN_DIM + HID) : ((PH == 1) ? (2 * HID) : HID);
    const int tid  = threadIdx.x;
    const int warp = tid >> 5, lane = tid & 31;
    const int grp  = lane >> 2, tig = lane & 3;
    const int wm0  = (warp >> 1) * 32, wn0 = (warp & 1) * 32;
    float* As = smem;             // [64][36] (pad 36 -> conflict-free frag loads)
    float* Bs = smem + 64 * 36;   // [64][36]

#pragma unroll
    for (int ma = 0; ma < 2; ma++)
#pragma unroll
        for (int na = 0; na < 4; na++)
#pragma unroll
            for (int i = 0; i < 4; i++) acc[ma][na][i] = 0.f;

    float4 ra[4], rb[4];
    fetchAB<PH>(0, m0, j0, A0, A1, B0, B1, ra, rb);

#pragma unroll 1
    for (int kb = 0; kb < KTOT; kb += 32) {
        __syncthreads();
#pragma unroll
        for (int r = 0; r < 4; r++) {
            const int item = tid + 128 * r;
            const int row  = item >> 3;
            const int c4   = 4 * (item & 7);
            float4 v = ra[r];
            v.x = rtf32(v.x); v.y = rtf32(v.y); v.z = rtf32(v.z); v.w = rtf32(v.w);
            *reinterpret_cast<float4*>(&As[row * 36 + c4]) = v;
            float4 w = rb[r];
            w.x = rtf32(w.x); w.y = rtf32(w.y); w.z = rtf32(w.z); w.w = rtf32(w.w);
            *reinterpret_cast<float4*>(&Bs[row * 36 + c4]) = w;
        }
        if (kb + 32 < KTOT) fetchAB<PH>(kb + 32, m0, j0, A0, A1, B0, B1, ra, rb);
        __syncthreads();
#pragma unroll
        for (int s = 0; s < 4; s++) {
            const int kk = 8 * s;
            uint32_t af[2][4], bf[4][2];
#pragma unroll
            for (int ma = 0; ma < 2; ma++) {
                const float* p = &As[(wm0 + 16 * ma + grp) * 36 + kk + tig];
                af[ma][0] = __float_as_uint(p[0]);
                af[ma][1] = __float_as_uint(p[8 * 36]);
                af[ma][2] = __float_as_uint(p[4]);
                af[ma][3] = __float_as_uint(p[8 * 36 + 4]);
            }
#pragma unroll
            for (int na = 0; na < 4; na++) {
                const float* p = &Bs[(wn0 + 8 * na + grp) * 36 + kk + tig];
                bf[na][0] = __float_as_uint(p[0]);
                bf[na][1] = __float_as_uint(p[4]);
            }
#pragma unroll
            for (int ma = 0; ma < 2; ma++)
#pragma unroll
                for (int na = 0; na < 4; na++) mma_tf32(acc[ma][na], af[ma], bf[na]);
        }
    }
}

// Fused LSTM-cell epilogue: stage gate tile in smem (aliases As/Bs), then each
// thread computes 8 (batch, hidden) cells and writes h (tf32-rounded) and c.
__device__ __forceinline__ void cell_epilogue(
    float (&acc)[2][4][4], float* smem, int m0, int j0,
    const float* __restrict__ bi, const float* __restrict__ bh,
    float* __restrict__ cbuf, float* __restrict__ hw) {
    float* gates = smem;  // [64][68]
    const int tid  = threadIdx.x;
    const int warp = tid >> 5, lane = tid & 31;
    const int grp  = lane >> 2, tig = lane & 3;
    const int wm0  = (warp >> 1) * 32, wn0 = (warp & 1) * 32;
    __syncthreads();  // all warps done reading As/Bs
#pragma unroll
    for (int ma = 0; ma < 2; ma++)
#pragma unroll
        for (int na = 0; na < 4; na++) {
            const int r0 = wm0 + 16 * ma + grp;
            const int c  = wn0 + 8 * na + 2 * tig;
            gates[r0 * 68 + c]           = acc[ma][na][0];
            gates[r0 * 68 + c + 1]       = acc[ma][na][1];
            gates[(r0 + 8) * 68 + c]     = acc[ma][na][2];
            gates[(r0 + 8) * 68 + c + 1] = acc[ma][na][3];
        }
    __syncthreads();
#pragma unroll
    for (int rep = 0; rep < 8; rep++) {
        const int it = tid + 128 * rep;
        const int m = it >> 4, jj = it & 15;
        const int b = m0 + m, j = j0 + jj;
        const float iv = gates[m * 68 + jj]      + bi[j]           + bh[j];
        const float fv = gates[m * 68 + 16 + jj] + bi[HID + j]     + bh[HID + j];
        const float gv = gates[m * 68 + 32 + jj] + bi[2 * HID + j] + bh[2 * HID + j];
        const float ov = gates[m * 68 + 48 + jj] + bi[3 * HID + j] + bh[3 * HID + j];
        const float c_old = cbuf[b * HID + j];
        const float cn = fmaf(sigf(fv), c_old, sigf(iv) * tanhf(gv));
        const float hn = sigf(ov) * tanhf(cn);
        cbuf[b * HID + j] = cn;
        hw[b * HID + j]   = rtf32(hn);
    }
}

__device__ __forceinline__ void linear_epilogue(
    float (&acc)[2][4][4], int m0, int tt,
    const float* __restrict__ blin, float* __restrict__ out) {
    const int tid  = threadIdx.x;
    const int warp = tid >> 5, lane = tid & 31;
    const int grp  = lane >> 2, tig = lane & 3;
    const int wm0  = (warp >> 1) * 32, wn0 = (warp & 1) * 32;
    const long row_stride = (long)T_STEPS * OUT_DIM;
#pragma unroll
    for (int ma = 0; ma < 2; ma++)
#pragma unroll
        for (int na = 0; na < 4; na++) {
            const int r = m0 + wm0 + 16 * ma + grp;
            const int c = wn0 + 8 * na + 2 * tig;
            float* o = out + (long)r * row_stride + tt * OUT_DIM + c;
            o[0] = acc[ma][na][0] + blin[c];
            o[1] = acc[ma][na][1] + blin[c + 1];
            float* o2 = o + 8 * row_stride;
            o2[0] = acc[ma][na][2] + blin[c];
            o2[1] = acc[ma][na][3] + blin[c + 1];
        }
}

__global__ void prep_kernel() {
    const int n = BATCH * HID;
    const int i = blockIdx.x * blockDim.x + threadIdx.x;
    if (i == 0) { g_count = 0; g_gen = 0; }
    for (int k = i; k < n; k += blockDim.x * gridDim.x) {
        g_h0[0][k] = 0.f; g_h0[1][k] = 0.f; g_c0[k] = 0.f;
        g_h1[0][k] = 0.f; g_h1[1][k] = 0.f; g_c1[k] = 0.f;
    }
}

__global__ void __launch_bounds__(128, 1) lstm_persistent(
    const float* __restrict__ x,
    const float* __restrict__ Wih0, const float* __restrict__ Whh0,
    const float* __restrict__ bih0, const float* __restrict__ bhh0,
    const float* __restrict__ Wih1, const float* __restrict__ Whh1,
    const float* __restrict__ bih1, const float* __restrict__ bhh1,
    const float* __restrict__ Wlin, const float* __restrict__ blin,
    float* __restrict__ out) {
    __shared__ __align__(16) float smem[2 * 64 * 36];
    const int bid = blockIdx.x;
    unsigned gen = 0;
    const int mi = bid >> 5, jn = bid & 31;  // valid for bid < 128
    const int m0g = mi * 64, j0 = jn * 16;
    float acc[2][4][4];

    for (int t = 0; t < T_STEPS; t++) {
        const int rp = t & 1, wp = rp ^ 1;
        if (bid < 128) {
            // Phase A: layer-0 gates + cell
            run_gemm<0>(x + (size_t)t * BATCH * IN_DIM, g_h0[rp], Wih0, Whh0,
                        m0g, j0, smem, acc);
            cell_epilogue(acc, smem, m0g, j0, bih0, bhh0, g_c0, g_h0[wp]);
        } else if (t > 0) {
            // Output linear for the previous step (runs concurrently w/ phase A)
            run_gemm<2>(g_h1[rp], nullptr, Wlin, nullptr,
                        (bid - 128) * 64, 0, smem, acc);
            linear_epilogue(acc, (bid - 128) * 64, t - 1, blin, out);
        }
        grid_sync(gen);
        if (bid < 128) {
            // Phase B: layer-1 gates + cell
            run_gemm<1>(g_h0[wp], g_h1[rp], Wih1, Whh1, m0g, j0, smem, acc);
            cell_epilogue(acc, smem, m0g, j0, bih1, bhh1, g_c1, g_h1[wp]);
        }
        grid_sync(gen);
    }
    // Final output linear for t = T-1 (h1 state lives in buffer parity T&1 == 0)
    if (bid >= 128) {
        run_gemm<2>(g_h1[0], nullptr, Wlin, nullptr,
                    (bid - 128) * 64, 0, smem, acc);
        linear_epilogue(acc, (bid - 128) * 64, T_STEPS - 1, blin, out);
    }
}

extern "C" void kernel_launch(void* const* d_in, const int* in_sizes, int n_in,
                              void* d_out, int out_size) {
    (void)in_sizes; (void)n_in; (void)out_size;
    const float* x    = (const float*)d_in[0];
    const float* Wih0 = (const float*)d_in[1];
    const float* Whh0 = (const float*)d_in[2];
    const float* bih0 = (const float*)d_in[3];
    const float* bhh0 = (const float*)d_in[4];
    const float* Wih1 = (const float*)d_in[5];
    const float* Whh1 = (const float*)d_in[6];
    const float* bih1 = (const float*)d_in[7];
    const float* bhh1 = (const float*)d_in[8];
    const float* Wlin = (const float*)d_in[9];
    const float* blin = (const float*)d_in[10];
    // d_in[11] = future (always 0) — ignored.
    float* out = (float*)d_out;

    prep_kernel<<<128, 256>>>();
    lstm_persistent<<<NCTA, 128>>>(x, Wih0, Whh0, bih0, bhh0,
                                   Wih1, Whh1, bih1, bhh1, Wlin, blin, out);
}

// round 3
// speedup vs baseline: 1.0057x; 1.0057x over previous
#include <cuda_runtime.h>
#include <cstdint>

// ---------------------------------------------------------------------------
// LSTMPredictor: 2-layer LSTM (H=512) over T=512 steps, B=256, IN=64, OUT=64.
// Persistent-kernel design: 132 co-resident CTAs, grid barrier between the two
// recurrent GEMM phases of each timestep. TF32 mma.sync with fp32 accumulate.
//
// Phase A (per step t): gates0 = [x_t | h0_old] @ [W_ih0 | W_hh0]^T  (K=576)
//                       -> LSTM cell -> h0_new, c0   (fused epilogue)
//          + 4 CTAs compute the output linear for step t-1 in parallel.
// Phase B:              gates1 = [h0_new | h1_old] @ [W_ih1 | W_hh1]^T (K=1024)
//                       -> LSTM cell -> h1_new, c1
//
// Tiling: gemm tiles are 64 rows (batch) x 64 gate-cols, where the 64 columns
// are 4 groups of 16 matching columns from gates i,f,g,o -> the cell is local
// to the CTA. 128 gemm tiles (4 M x 32 column-groups) + 4 linear tiles = 132.
// ---------------------------------------------------------------------------

namespace {
constexpr int T_STEPS = 512;
constexpr int BATCH   = 256;
constexpr int IN_DIM  = 64;
constexpr int HID     = 512;
constexpr int OUT_DIM = 64;
constexpr int NCTA    = 132;
}

// Persistent state (static device scratch; allocation-free).
__device__ float g_h0[2][BATCH * HID];
__device__ float g_h1[2][BATCH * HID];
__device__ float g_c0[BATCH * HID];
__device__ float g_c1[BATCH * HID];
__device__ unsigned g_count;
__device__ unsigned g_gen;

__device__ __forceinline__ float rtf32(float v) {
    asm("cvt.rna.tf32.f32 %0, %1;" : "=f"(v) : "f"(v));
    return v;
}

__device__ __forceinline__ float sigf(float v) {
    return 1.0f / (1.0f + __expf(-v));
}

__device__ __forceinline__ void mma_tf32(float (&d)[4], const uint32_t (&a)[4],
                                         const uint32_t (&b)[2]) {
    asm volatile(
        "mma.sync.aligned.m16n8k8.row.col.f32.tf32.tf32.f32 "
        "{%0,%1,%2,%3},{%4,%5,%6,%7},{%8,%9},{%0,%1,%2,%3};"
        : "+f"(d[0]), "+f"(d[1]), "+f"(d[2]), "+f"(d[3])
        : "r"(a[0]), "r"(a[1]), "r"(a[2]), "r"(a[3]), "r"(b[0]), "r"(b[1]));
}

// Grid-wide sense-reversal barrier. All CTAs resident (132 <= 148 SMs).
__device__ __forceinline__ void grid_sync(unsigned &gen) {
    const unsigned target = gen + 1;
    __syncthreads();
    if (threadIdx.x == 0) {
        __threadfence();
        unsigned prev = atomicAdd(&g_count, 1u);
        if (prev == gridDim.x - 1) {
            g_count = 0;
            __threadfence();
            atomicExch(&g_gen, target);
        } else {
            const volatile unsigned* p = &g_gen;
            while (*p != target) {}
            __threadfence();
        }
    }
    __syncthreads();
    gen = target;
}

// ---------------------------------------------------------------------------
// Tiled GEMM: 64x64 output tile, K-blocked by 32, 4 warps (2x2 of 32x32),
// m16n8k8 tf32 mma. A = activations (K-major), B = weight rows (K-major).
// PH==0: A = [x_t | h0_old], B rows from W_ih0/W_hh0, K=576
// PH==1: A = [h0_new | h1_old], B rows from W_ih1/W_hh1, K=1024
// PH==2: A = h1, B rows = W_lin, K=512  (output linear)
// For PH 0/1, the tile's local column n_local maps to global gate row
//   n = (n_local/16)*512 + j0 + (n_local%16)   (4 gate groups of 16 columns)
// ---------------------------------------------------------------------------
template <int PH>
__device__ __forceinline__ void fetchAB(
    int kb, int m0, int j0,
    const float* __restrict__ A0, const float* __restrict__ A1,
    const float* __restrict__ B0, const float* __restrict__ B1,
    float4 (&ra)[4], float4 (&rb)[4]) {
    const int tid = threadIdx.x;
#pragma unroll
    for (int r = 0; r < 4; r++) {
        const int item = tid + 128 * r;
        const int row  = item >> 3;
        const int k    = kb + 4 * (item & 7);
        // A tile: recurrent state -> L2-coherent loads (.cg); x is immutable.
        if (PH == 0) {
            if (k < IN_DIM)
                ra[r] = *reinterpret_cast<const float4*>(A0 + (m0 + row) * IN_DIM + k);
            else
                ra[r] = __ldcg(reinterpret_cast<const float4*>(A1 + (m0 + row) * HID + (k - IN_DIM)));
        } else if (PH == 1) {
            if (k < HID)
                ra[r] = __ldcg(reinterpret_cast<const float4*>(A0 + (m0 + row) * HID + k));
            else
                ra[r] = __ldcg(reinterpret_cast<const float4*>(A1 + (m0 + row) * HID + (k - HID)));
        } else {
            ra[r] = __ldcg(reinterpret_cast<const float4*>(A0 + (m0 + row) * HID + k));
        }
        // B tile: weights (immutable inputs).
        if (PH == 2) {
            rb[r] = *reinterpret_cast<const float4*>(B0 + row * HID + k);
        } else {
            const int n = ((row >> 4) << 9) + j0 + (row & 15);
            if (PH == 0) {
                if (k < IN_DIM)
                    rb[r] = *reinterpret_cast<const float4*>(B0 + n * IN_DIM + k);
                else
                    rb[r] = *reinterpret_cast<const float4*>(B1 + n * HID + (k - IN_DIM));
            } else {
                if (k < HID)
                    rb[r] = *reinterpret_cast<const float4*>(B0 + n * HID + k);
                else
                    rb[r] = *reinterpret_cast<const float4*>(B1 + n * HID + (k - HID));
            }
        }
    }
}

template <int PH>
__device__ __forceinline__ void run_gemm(
    const float* __restrict__ A0, const float* __restrict__ A1,
    const float* __restrict__ B0, const float* __restrict__ B1,
    int m0, int j0, float* smem, float (&acc)[2][4][4]) {
    constexpr int KTOT = (PH == 0) ? (IN_DIM + HID) : ((PH == 1) ? (2 * HID) : HID);
    const int tid  = threadIdx.x;
    const int warp = tid >> 5, lane = tid & 31;
    const int grp  = lane >> 2, tig = lane & 3;
    const int wm0  = (warp >> 1) * 32, wn0 = (warp & 1) * 32;
    float* As = smem;             // [64][36] (pad 36 -> conflict-free frag loads)
    float* Bs = smem + 64 * 36;   // [64][36]

#pragma unroll
    for (int ma = 0; ma < 2; ma++)
#pragma unroll
        for (int na = 0; na < 4; na++)
#pragma unroll
            for (int i = 0; i < 4; i++) acc[ma][na][i] = 0.f;

    float4 ra[4], rb[4];
    fetchAB<PH>(0, m0, j0, A0, A1, B0, B1, ra, rb);

#pragma unroll 1
    for (int kb = 0; kb < KTOT; kb += 32) {
        __syncthreads();
#pragma unroll
        for (int r = 0; r < 4; r++) {
            const int item = tid + 128 * r;
            const int row  = item >> 3;
            const int c4   = 4 * (item & 7);
            float4 v = ra[r];
            v.x = rtf32(v.x); v.y = rtf32(v.y); v.z = rtf32(v.z); v.w = rtf32(v.w);
            *reinterpret_cast<float4*>(&As[row * 36 + c4]) = v;
            float4 w = rb[r];
            w.x = rtf32(w.x); w.y = rtf32(w.y); w.z = rtf32(w.z); w.w = rtf32(w.w);
            *reinterpret_cast<float4*>(&Bs[row * 36 + c4]) = w;
        }
        if (kb + 32 < KTOT) fetchAB<PH>(kb + 32, m0, j0, A0, A1, B0, B1, ra, rb);
        __syncthreads();
#pragma unroll
        for (int s = 0; s < 4; s++) {
            const int kk = 8 * s;
            uint32_t af[2][4], bf[4][2];
#pragma unroll
            for (int ma = 0; ma < 2; ma++) {
                const float* p = &As[(wm0 + 16 * ma + grp) * 36 + kk + tig];
                af[ma][0] = __float_as_uint(p[0]);
                af[ma][1] = __float_as_uint(p[8 * 36]);
                af[ma][2] = __float_as_uint(p[4]);
                af[ma][3] = __float_as_uint(p[8 * 36 + 4]);
            }
#pragma unroll
            for (int na = 0; na < 4; na++) {
                const float* p = &Bs[(wn0 + 8 * na + grp) * 36 + kk + tig];
                bf[na][0] = __float_as_uint(p[0]);
                bf[na][1] = __float_as_uint(p[4]);
            }
#pragma unroll
            for (int ma = 0; ma < 2; ma++)
#pragma unroll
                for (int na = 0; na < 4; na++) mma_tf32(acc[ma][na], af[ma], bf[na]);
        }
    }
}

// Fused LSTM-cell epilogue: stage gate tile in smem (aliases As/Bs), then each
// thread computes 8 (batch, hidden) cells and writes h (tf32-rounded) and c.
__device__ __forceinline__ void cell_epilogue(
    float (&acc)[2][4][4], float* smem, int m0, int j0,
    const float* __restrict__ bi, const float* __restrict__ bh,
    float* __restrict__ cbuf, float* __restrict__ hw) {
    float* gates = smem;  // [64][68]
    const int tid  = threadIdx.x;
    const int warp = tid >> 5, lane = tid & 31;
    const int grp  = lane >> 2, tig = lane & 3;
    const int wm0  = (warp >> 1) * 32, wn0 = (warp & 1) * 32;
    __syncthreads();  // all warps done reading As/Bs
#pragma unroll
    for (int ma = 0; ma < 2; ma++)
#pragma unroll
        for (int na = 0; na < 4; na++) {
            const int r0 = wm0 + 16 * ma + grp;
            const int c  = wn0 + 8 * na + 2 * tig;
            gates[r0 * 68 + c]           = acc[ma][na][0];
            gates[r0 * 68 + c + 1]       = acc[ma][na][1];
            gates[(r0 + 8) * 68 + c]     = acc[ma][na][2];
            gates[(r0 + 8) * 68 + c + 1] = acc[ma][na][3];
        }
    __syncthreads();
#pragma unroll
    for (int rep = 0; rep < 8; rep++) {
        const int it = tid + 128 * rep;
        const int m = it >> 4, jj = it & 15;
        const int b = m0 + m, j = j0 + jj;
        const float iv = gates[m * 68 + jj]      + bi[j]           + bh[j];
        const float fv = gates[m * 68 + 16 + jj] + bi[HID + j]     + bh[HID + j];
        const float gv = gates[m * 68 + 32 + jj] + bi[2 * HID + j] + bh[2 * HID + j];
        const float ov = gates[m * 68 + 48 + jj] + bi[3 * HID + j] + bh[3 * HID + j];
        const float c_old = cbuf[b * HID + j];
        const float cn = fmaf(sigf(fv), c_old, sigf(iv) * tanhf(gv));
        const float hn = sigf(ov) * tanhf(cn);
        cbuf[b * HID + j] = cn;
        hw[b * HID + j]   = rtf32(hn);
    }
}

__device__ __forceinline__ void linear_epilogue(
    float (&acc)[2][4][4], int m0, int tt,
    const float* __restrict__ blin, float* __restrict__ out) {
    const int tid  = threadIdx.x;
    const int warp = tid >> 5, lane = tid & 31;
    const int grp  = lane >> 2, tig = lane & 3;
    const int wm0  = (warp >> 1) * 32, wn0 = (warp & 1) * 32;
    const long row_stride = (long)T_STEPS * OUT_DIM;
#pragma unroll
    for (int ma = 0; ma < 2; ma++)
#pragma unroll
        for (int na = 0; na < 4; na++) {
            const int r = m0 + wm0 + 16 * ma + grp;
            const int c = wn0 + 8 * na + 2 * tig;
            float* o = out + (long)r * row_stride + tt * OUT_DIM + c;
            o[0] = acc[ma][na][0] + blin[c];
            o[1] = acc[ma][na][1] + blin[c + 1];
            float* o2 = o + 8 * row_stride;
            o2[0] = acc[ma][na][2] + blin[c];
            o2[1] = acc[ma][na][3] + blin[c + 1];
        }
}

__global__ void prep_kernel() {
    const int n = BATCH * HID;
    const int i = blockIdx.x * blockDim.x + threadIdx.x;
    if (i == 0) { g_count = 0; g_gen = 0; }
    for (int k = i; k < n; k += blockDim.x * gridDim.x) {
        g_h0[0][k] = 0.f; g_h0[1][k] = 0.f; g_c0[k] = 0.f;
        g_h1[0][k] = 0.f; g_h1[1][k] = 0.f; g_c1[k] = 0.f;
    }
}

__global__ void __launch_bounds__(128, 1) lstm_persistent(
    const float* __restrict__ x,
    const float* __restrict__ Wih0, const float* __restrict__ Whh0,
    const float* __restrict__ bih0, const float* __restrict__ bhh0,
    const float* __restrict__ Wih1, const float* __restrict__ Whh1,
    const float* __restrict__ bih1, const float* __restrict__ bhh1,
    const float* __restrict__ Wlin, const float* __restrict__ blin,
    float* __restrict__ out) {
    __shared__ __align__(16) float smem[2 * 64 * 36];
    const int bid = blockIdx.x;
    unsigned gen = 0;
    const int mi = bid >> 5, jn = bid & 31;  // valid for bid < 128
    const int m0g = mi * 64, j0 = jn * 16;
    float acc[2][4][4];

    for (int t = 0; t < T_STEPS; t++) {
        const int rp = t & 1, wp = rp ^ 1;
        if (bid < 128) {
            // Phase A: layer-0 gates + cell
            run_gemm<0>(x + (size_t)t * BATCH * IN_DIM, g_h0[rp], Wih0, Whh0,
                        m0g, j0, smem, acc);
            cell_epilogue(acc, smem, m0g, j0, bih0, bhh0, g_c0, g_h0[wp]);
        } else if (t > 0) {
            // Output linear for the previous step (runs concurrently w/ phase A)
            run_gemm<2>(g_h1[rp], nullptr, Wlin, nullptr,
                        (bid - 128) * 64, 0, smem, acc);
            linear_epilogue(acc, (bid - 128) * 64, t - 1, blin, out);
        }
        grid_sync(gen);
        if (bid < 128) {
            // Phase B: layer-1 gates + cell
            run_gemm<1>(g_h0[wp], g_h1[rp], Wih1, Whh1, m0g, j0, smem, acc);
            cell_epilogue(acc, smem, m0g, j0, bih1, bhh1, g_c1, g_h1[wp]);
        }
        grid_sync(gen);
    }
    // Final output linear for t = T-1 (h1 state lives in buffer parity T&1 == 0)
    if (bid >= 128) {
        run_gemm<2>(g_h1[0], nullptr, Wlin, nullptr,
                    (bid - 128) * 64, 0, smem, acc);
        linear_epilogue(acc, (bid - 128) * 64, T_STEPS - 1, blin, out);
    }
}

extern "C" void kernel_launch(void* const* d_in, const int* in_sizes, int n_in,
                              void* d_out, int out_size) {
    (void)in_sizes; (void)n_in; (void)out_size;
    const float* x    = (const float*)d_in[0];
    const float* Wih0 = (const float*)d_in[1];
    const float* Whh0 = (const float*)d_in[2];
    const float* bih0 = (const float*)d_in[3];
    const float* bhh0 = (const float*)d_in[4];
    const float* Wih1 = (const float*)d_in[5];
    const float* Whh1 = (const float*)d_in[6];
    const float* bih1 = (const float*)d_in[7];
    const float* bhh1 = (const float*)d_in[8];
    const float* Wlin = (const float*)d_in[9];
    const float* blin = (const float*)d_in[10];
    // d_in[11] = future (always 0) — ignored.
    float* out = (float*)d_out;

    prep_kernel<<<128, 256>>>();
    lstm_persistent<<<NCTA, 128>>>(x, Wih0, Whh0, bih0, bhh0,
                                   Wih1, Whh1, bih1, bhh1, Wlin, blin, out);
}

// round 4
// speedup vs baseline: 1.0305x; 1.0246x over previous
#include <cuda_runtime.h>
#include <cstdint>

// ---------------------------------------------------------------------------
// LSTMPredictor: 2-layer LSTM (H=512) over T=512 steps, B=256, IN=64, OUT=64.
// Persistent-kernel design: 132 co-resident CTAs, grid barrier between the two
// recurrent GEMM phases of each timestep. TF32 mma.sync with fp32 accumulate.
//
// Phase A (per step t): gates0 = [x_t | h0_old] @ [W_ih0 | W_hh0]^T  (K=576)
//                       -> LSTM cell -> h0_new, c0   (fused epilogue)
//          + 4 CTAs compute the output linear for step t-1 in parallel.
// Phase B:              gates1 = [h0_new | h1_old] @ [W_ih1 | W_hh1]^T (K=1024)
//                       -> LSTM cell -> h1_new, c1
//
// Tiling: gemm tiles are 64 rows (batch) x 64 gate-cols, where the 64 columns
// are 4 groups of 16 matching columns from gates i,f,g,o -> the cell is local
// to the CTA. 128 gemm tiles (4 M x 32 column-groups) + 4 linear tiles = 132.
// ---------------------------------------------------------------------------

namespace {
constexpr int T_STEPS = 512;
constexpr int BATCH   = 256;
constexpr int IN_DIM  = 64;
constexpr int HID     = 512;
constexpr int OUT_DIM = 64;
constexpr int NCTA    = 132;
}

// Persistent state (static device scratch; allocation-free).
__device__ float g_h0[2][BATCH * HID];
__device__ float g_h1[2][BATCH * HID];
__device__ float g_c0[BATCH * HID];
__device__ float g_c1[BATCH * HID];
__device__ unsigned g_count;
__device__ unsigned g_gen;

__device__ __forceinline__ float rtf32(float v) {
    asm("cvt.rna.tf32.f32 %0, %1;" : "=f"(v) : "f"(v));
    return v;
}

__device__ __forceinline__ float sigf(float v) {
    return 1.0f / (1.0f + __expf(-v));
}

__device__ __forceinline__ void mma_tf32(float (&d)[4], const uint32_t (&a)[4],
                                         const uint32_t (&b)[2]) {
    asm volatile(
        "mma.sync.aligned.m16n8k8.row.col.f32.tf32.tf32.f32 "
        "{%0,%1,%2,%3},{%4,%5,%6,%7},{%8,%9},{%0,%1,%2,%3};"
        : "+f"(d[0]), "+f"(d[1]), "+f"(d[2]), "+f"(d[3])
        : "r"(a[0]), "r"(a[1]), "r"(a[2]), "r"(a[3]), "r"(b[0]), "r"(b[1]));
}

// Grid-wide sense-reversal barrier. All CTAs resident (132 <= 148 SMs).
__device__ __forceinline__ void grid_sync(unsigned &gen) {
    const unsigned target = gen + 1;
    __syncthreads();
    if (threadIdx.x == 0) {
        __threadfence();
        unsigned prev = atomicAdd(&g_count, 1u);
        if (prev == gridDim.x - 1) {
            g_count = 0;
            __threadfence();
            atomicExch(&g_gen, target);
        } else {
            const volatile unsigned* p = &g_gen;
            while (*p != target) {}
            __threadfence();
        }
    }
    __syncthreads();
    gen = target;
}

// ---------------------------------------------------------------------------
// Tiled GEMM: 64x64 output tile, K-blocked by 32, 4 warps (2x2 of 32x32),
// m16n8k8 tf32 mma. A = activations (K-major), B = weight rows (K-major).
// PH==0: A = [x_t | h0_old], B rows from W_ih0/W_hh0, K=576
// PH==1: A = [h0_new | h1_old], B rows from W_ih1/W_hh1, K=1024
// PH==2: A = h1, B rows = W_lin, K=512  (output linear)
// For PH 0/1, the tile's local column n_local maps to global gate row
//   n = (n_local/16)*512 + j0 + (n_local%16)   (4 gate groups of 16 columns)
// ---------------------------------------------------------------------------
template <int PH>
__device__ __forceinline__ void fetchAB(
    int kb, int m0, int j0,
    const float* __restrict__ A0, const float* __restrict__ A1,
    const float* __restrict__ B0, const float* __restrict__ B1,
    float4 (&ra)[4], float4 (&rb)[4]) {
    const int tid = threadIdx.x;
#pragma unroll
    for (int r = 0; r < 4; r++) {
        const int item = tid + 128 * r;
        const int row  = item >> 3;
        const int k    = kb + 4 * (item & 7);
        // A tile: recurrent state -> L2-coherent loads (.cg); x is immutable.
        if (PH == 0) {
            if (k < IN_DIM)
                ra[r] = *reinterpret_cast<const float4*>(A0 + (m0 + row) * IN_DIM + k);
            else
                ra[r] = __ldcg(reinterpret_cast<const float4*>(A1 + (m0 + row) * HID + (k - IN_DIM)));
        } else if (PH == 1) {
            if (k < HID)
                ra[r] = __ldcg(reinterpret_cast<const float4*>(A0 + (m0 + row) * HID + k));
            else
                ra[r] = __ldcg(reinterpret_cast<const float4*>(A1 + (m0 + row) * HID + (k - HID)));
        } else {
            ra[r] = __ldcg(reinterpret_cast<const float4*>(A0 + (m0 + row) * HID + k));
        }
        // B tile: weights (immutable inputs).
        if (PH == 2) {
            rb[r] = *reinterpret_cast<const float4*>(B0 + row * HID + k);
        } else {
            const int n = ((row >> 4) << 9) + j0 + (row & 15);
            if (PH == 0) {
                if (k < IN_DIM)
                    rb[r] = *reinterpret_cast<const float4*>(B0 + n * IN_DIM + k);
                else
                    rb[r] = *reinterpret_cast<const float4*>(B1 + n * HID + (k - IN_DIM));
            } else {
                if (k < HID)
                    rb[r] = *reinterpret_cast<const float4*>(B0 + n * HID + k);
                else
                    rb[r] = *reinterpret_cast<const float4*>(B1 + n * HID + (k - HID));
            }
        }
    }
}

template <int PH>
__device__ __forceinline__ void run_gemm(
    const float* __restrict__ A0, const float* __restrict__ A1,
    const float* __restrict__ B0, const float* __restrict__ B1,
    int m0, int j0, float* smem, float (&acc)[2][4][4]) {
    constexpr int KTOT = (PH == 0) ? (IN_DIM + HID) : ((PH == 1) ? (2 * HID) : HID);
    const int tid  = threadIdx.x;
    const int warp = tid >> 5, lane = tid & 31;
    const int grp  = lane >> 2, tig = lane & 3;
    const int wm0  = (warp >> 1) * 32, wn0 = (warp & 1) * 32;
    float* As = smem;             // [64][36] (pad 36 -> conflict-free frag loads)
    float* Bs = smem + 64 * 36;   // [64][36]

#pragma unroll
    for (int ma = 0; ma < 2; ma++)
#pragma unroll
        for (int na = 0; na < 4; na++)
#pragma unroll
            for (int i = 0; i < 4; i++) acc[ma][na][i] = 0.f;

    float4 ra[4], rb[4];
    fetchAB<PH>(0, m0, j0, A0, A1, B0, B1, ra, rb);

#pragma unroll 1
    for (int kb = 0; kb < KTOT; kb += 32) {
        __syncthreads();
#pragma unroll
        for (int r = 0; r < 4; r++) {
            const int item = tid + 128 * r;
            const int row  = item >> 3;
            const int c4   = 4 * (item & 7);
            float4 v = ra[r];
            v.x = rtf32(v.x); v.y = rtf32(v.y); v.z = rtf32(v.z); v.w = rtf32(v.w);
            *reinterpret_cast<float4*>(&As[row * 36 + c4]) = v;
            float4 w = rb[r];
            w.x = rtf32(w.x); w.y = rtf32(w.y); w.z = rtf32(w.z); w.w = rtf32(w.w);
            *reinterpret_cast<float4*>(&Bs[row * 36 + c4]) = w;
        }
        if (kb + 32 < KTOT) fetchAB<PH>(kb + 32, m0, j0, A0, A1, B0, B1, ra, rb);
        __syncthreads();
#pragma unroll
        for (int s = 0; s < 4; s++) {
            const int kk = 8 * s;
            uint32_t af[2][4], bf[4][2];
#pragma unroll
            for (int ma = 0; ma < 2; ma++) {
                const float* p = &As[(wm0 + 16 * ma + grp) * 36 + kk + tig];
                af[ma][0] = __float_as_uint(p[0]);
                af[ma][1] = __float_as_uint(p[8 * 36]);
                af[ma][2] = __float_as_uint(p[4]);
                af[ma][3] = __float_as_uint(p[8 * 36 + 4]);
            }
#pragma unroll
            for (int na = 0; na < 4; na++) {
                const float* p = &Bs[(wn0 + 8 * na + grp) * 36 + kk + tig];
                bf[na][0] = __float_as_uint(p[0]);
                bf[na][1] = __float_as_uint(p[4]);
            }
#pragma unroll
            for (int ma = 0; ma < 2; ma++)
#pragma unroll
                for (int na = 0; na < 4; na++) mma_tf32(acc[ma][na], af[ma], bf[na]);
        }
    }
}

// Fused LSTM-cell epilogue: stage gate tile in smem (aliases As/Bs), then each
// thread computes 8 (batch, hidden) cells and writes h (tf32-rounded) and c.
__device__ __forceinline__ void cell_epilogue(
    float (&acc)[2][4][4], float* smem, int m0, int j0,
    const float* __restrict__ bi, const float* __restrict__ bh,
    float* __restrict__ cbuf, float* __restrict__ hw) {
    float* gates = smem;  // [64][68]
    const int tid  = threadIdx.x;
    const int warp = tid >> 5, lane = tid & 31;
    const int grp  = lane >> 2, tig = lane & 3;
    const int wm0  = (warp >> 1) * 32, wn0 = (warp & 1) * 32;
    __syncthreads();  // all warps done reading As/Bs
#pragma unroll
    for (int ma = 0; ma < 2; ma++)
#pragma unroll
        for (int na = 0; na < 4; na++) {
            const int r0 = wm0 + 16 * ma + grp;
            const int c  = wn0 + 8 * na + 2 * tig;
            gates[r0 * 68 + c]           = acc[ma][na][0];
            gates[r0 * 68 + c + 1]       = acc[ma][na][1];
            gates[(r0 + 8) * 68 + c]     = acc[ma][na][2];
            gates[(r0 + 8) * 68 + c + 1] = acc[ma][na][3];
        }
    __syncthreads();
#pragma unroll
    for (int rep = 0; rep < 8; rep++) {
        const int it = tid + 128 * rep;
        const int m = it >> 4, jj = it & 15;
        const int b = m0 + m, j = j0 + jj;
        const float iv = gates[m * 68 + jj]      + bi[j]           + bh[j];
        const float fv = gates[m * 68 + 16 + jj] + bi[HID + j]     + bh[HID + j];
        const float gv = gates[m * 68 + 32 + jj] + bi[2 * HID + j] + bh[2 * HID + j];
        const float ov = gates[m * 68 + 48 + jj] + bi[3 * HID + j] + bh[3 * HID + j];
        const float c_old = cbuf[b * HID + j];
        const float cn = fmaf(sigf(fv), c_old, sigf(iv) * tanhf(gv));
        const float hn = sigf(ov) * tanhf(cn);
        cbuf[b * HID + j] = cn;
        hw[b * HID + j]   = rtf32(hn);
    }
}

__device__ __forceinline__ void linear_epilogue(
    float (&acc)[2][4][4], int m0, int tt,
    const float* __restrict__ blin, float* __restrict__ out) {
    const int tid  = threadIdx.x;
    const int warp = tid >> 5, lane = tid & 31;
    const int grp  = lane >> 2, tig = lane & 3;
    const int wm0  = (warp >> 1) * 32, wn0 = (warp & 1) * 32;
    const long row_stride = (long)T_STEPS * OUT_DIM;
#pragma unroll
    for (int ma = 0; ma < 2; ma++)
#pragma unroll
        for (int na = 0; na < 4; na++) {
            const int r = m0 + wm0 + 16 * ma + grp;
            const int c = wn0 + 8 * na + 2 * tig;
            float* o = out + (long)r * row_stride + tt * OUT_DIM + c;
            o[0] = acc[ma][na][0] + blin[c];
            o[1] = acc[ma][na][1] + blin[c + 1];
            float* o2 = o + 8 * row_stride;
            o2[0] = acc[ma][na][2] + blin[c];
            o2[1] = acc[ma][na][3] + blin[c + 1];
        }
}

__global__ void prep_kernel() {
    const int n = BATCH * HID;
    const int i = blockIdx.x * blockDim.x + threadIdx.x;
    if (i == 0) { g_count = 0; g_gen = 0; }
    for (int k = i; k < n; k += blockDim.x * gridDim.x) {
        g_h0[0][k] = 0.f; g_h0[1][k] = 0.f; g_c0[k] = 0.f;
        g_h1[0][k] = 0.f; g_h1[1][k] = 0.f; g_c1[k] = 0.f;
    }
}

__global__ void __launch_bounds__(128, 1) lstm_persistent(
    const float* __restrict__ x,
    const float* __restrict__ Wih0, const float* __restrict__ Whh0,
    const float* __restrict__ bih0, const float* __restrict__ bhh0,
    const float* __restrict__ Wih1, const float* __restrict__ Whh1,
    const float* __restrict__ bih1, const float* __restrict__ bhh1,
    const float* __restrict__ Wlin, const float* __restrict__ blin,
    float* __restrict__ out) {
    __shared__ __align__(16) float smem[2 * 64 * 36];
    const int bid = blockIdx.x;
    unsigned gen = 0;
    const int mi = bid >> 5, jn = bid & 31;  // valid for bid < 128
    const int m0g = mi * 64, j0 = jn * 16;
    float acc[2][4][4];

    for (int t = 0; t < T_STEPS; t++) {
        const int rp = t & 1, wp = rp ^ 1;
        if (bid < 128) {
            // Phase A: layer-0 gates + cell
            run_gemm<0>(x + (size_t)t * BATCH * IN_DIM, g_h0[rp], Wih0, Whh0,
                        m0g, j0, smem, acc);
            cell_epilogue(acc, smem, m0g, j0, bih0, bhh0, g_c0, g_h0[wp]);
        } else if (t > 0) {
            // Output linear for the previous step (runs concurrently w/ phase A)
            run_gemm<2>(g_h1[rp], nullptr, Wlin, nullptr,
                        (bid - 128) * 64, 0, smem, acc);
            linear_epilogue(acc, (bid - 128) * 64, t - 1, blin, out);
        }
        grid_sync(gen);
        if (bid < 128) {
            // Phase B: layer-1 gates + cell
            run_gemm<1>(g_h0[wp], g_h1[rp], Wih1, Whh1, m0g, j0, smem, acc);
            cell_epilogue(acc, smem, m0g, j0, bih1, bhh1, g_c1, g_h1[wp]);
        }
        grid_sync(gen);
    }
    // Final output linear for t = T-1 (h1 state lives in buffer parity T&1 == 0)
    if (bid >= 128) {
        run_gemm<2>(g_h1[0], nullptr, Wlin, nullptr,
                    (bid - 128) * 64, 0, smem, acc);
        linear_epilogue(acc, (bid - 128) * 64, T_STEPS - 1, blin, out);
    }
}

extern "C" void kernel_launch(void* const* d_in, const int* in_sizes, int n_in,
                              void* d_out, int out_size) {
    (void)in_sizes; (void)n_in; (void)out_size;
    const float* x    = (const float*)d_in[0];
    const float* Wih0 = (const float*)d_in[1];
    const float* Whh0 = (const float*)d_in[2];
    const float* bih0 = (const float*)d_in[3];
    const float* bhh0 = (const float*)d_in[4];
    const float* Wih1 = (const float*)d_in[5];
    const float* Whh1 = (const float*)d_in[6];
    const float* bih1 = (const float*)d_in[7];
    const float* bhh1 = (const float*)d_in[8];
    const float* Wlin = (const float*)d_in[9];
    const float* blin = (const float*)d_in[10];
    // d_in[11] = future (always 0) — ignored.
    float* out = (float*)d_out;

    prep_kernel<<<128, 256>>>();
    lstm_persistent<<<NCTA, 128>>>(x, Wih0, Whh0, bih0, bhh0,
                                   Wih1, Whh1, bih1, bhh1, Wlin, blin, out);
}

// round 5
// speedup vs baseline: 1.0319x; 1.0013x over previous
#include <cuda_runtime.h>
#include <cstdint>

// ---------------------------------------------------------------------------
// LSTMPredictor: 2-layer LSTM (H=512) over T=512 steps, B=256, IN=64, OUT=64.
// Persistent-kernel design: 132 co-resident CTAs, grid barrier between the two
// recurrent GEMM phases of each timestep. TF32 mma.sync with fp32 accumulate.
//
// Phase A (per step t): gates0 = [x_t | h0_old] @ [W_ih0 | W_hh0]^T  (K=576)
//                       -> LSTM cell -> h0_new, c0   (fused epilogue)
//          + 4 CTAs compute the output linear for step t-1 in parallel.
// Phase B:              gates1 = [h0_new | h1_old] @ [W_ih1 | W_hh1]^T (K=1024)
//                       -> LSTM cell -> h1_new, c1
//
// Tiling: gemm tiles are 64 rows (batch) x 64 gate-cols, where the 64 columns
// are 4 groups of 16 matching columns from gates i,f,g,o -> the cell is local
// to the CTA. 128 gemm tiles (4 M x 32 column-groups) + 4 linear tiles = 132.
// ---------------------------------------------------------------------------

namespace {
constexpr int T_STEPS = 512;
constexpr int BATCH   = 256;
constexpr int IN_DIM  = 64;
constexpr int HID     = 512;
constexpr int OUT_DIM = 64;
constexpr int NCTA    = 132;
}

// Persistent state (static device scratch; allocation-free).
__device__ float g_h0[2][BATCH * HID];
__device__ float g_h1[2][BATCH * HID];
__device__ float g_c0[BATCH * HID];
__device__ float g_c1[BATCH * HID];
__device__ unsigned g_count;
__device__ unsigned g_gen;

__device__ __forceinline__ float rtf32(float v) {
    asm("cvt.rna.tf32.f32 %0, %1;" : "=f"(v) : "f"(v));
    return v;
}

__device__ __forceinline__ float sigf(float v) {
    return 1.0f / (1.0f + __expf(-v));
}

__device__ __forceinline__ void mma_tf32(float (&d)[4], const uint32_t (&a)[4],
                                         const uint32_t (&b)[2]) {
    asm volatile(
        "mma.sync.aligned.m16n8k8.row.col.f32.tf32.tf32.f32 "
        "{%0,%1,%2,%3},{%4,%5,%6,%7},{%8,%9},{%0,%1,%2,%3};"
        : "+f"(d[0]), "+f"(d[1]), "+f"(d[2]), "+f"(d[3])
        : "r"(a[0]), "r"(a[1]), "r"(a[2]), "r"(a[3]), "r"(b[0]), "r"(b[1]));
}

// Grid-wide sense-reversal barrier. All CTAs resident (132 <= 148 SMs).
__device__ __forceinline__ void grid_sync(unsigned &gen) {
    const unsigned target = gen + 1;
    __syncthreads();
    if (threadIdx.x == 0) {
        __threadfence();
        unsigned prev = atomicAdd(&g_count, 1u);
        if (prev == gridDim.x - 1) {
            g_count = 0;
            __threadfence();
            atomicExch(&g_gen, target);
        } else {
            const volatile unsigned* p = &g_gen;
            while (*p != target) {}
            __threadfence();
        }
    }
    __syncthreads();
    gen = target;
}

// ---------------------------------------------------------------------------
// Tiled GEMM: 64x64 output tile, K-blocked by 32, 4 warps (2x2 of 32x32),
// m16n8k8 tf32 mma. A = activations (K-major), B = weight rows (K-major).
// PH==0: A = [x_t | h0_old], B rows from W_ih0/W_hh0, K=576
// PH==1: A = [h0_new | h1_old], B rows from W_ih1/W_hh1, K=1024
// PH==2: A = h1, B rows = W_lin, K=512  (output linear)
// For PH 0/1, the tile's local column n_local maps to global gate row
//   n = (n_local/16)*512 + j0 + (n_local%16)   (4 gate groups of 16 columns)
// ---------------------------------------------------------------------------
template <int PH>
__device__ __forceinline__ void fetchAB(
    int kb, int m0, int j0,
    const float* __restrict__ A0, const float* __restrict__ A1,
    const float* __restrict__ B0, const float* __restrict__ B1,
    float4 (&ra)[4], float4 (&rb)[4]) {
    const int tid = threadIdx.x;
#pragma unroll
    for (int r = 0; r < 4; r++) {
        const int item = tid + 128 * r;
        const int row  = item >> 3;
        const int k    = kb + 4 * (item & 7);
        // A tile: recurrent state -> L2-coherent loads (.cg); x is immutable.
        if (PH == 0) {
            if (k < IN_DIM)
                ra[r] = *reinterpret_cast<const float4*>(A0 + (m0 + row) * IN_DIM + k);
            else
                ra[r] = __ldcg(reinterpret_cast<const float4*>(A1 + (m0 + row) * HID + (k - IN_DIM)));
        } else if (PH == 1) {
            if (k < HID)
                ra[r] = __ldcg(reinterpret_cast<const float4*>(A0 + (m0 + row) * HID + k));
            else
                ra[r] = __ldcg(reinterpret_cast<const float4*>(A1 + (m0 + row) * HID + (k - HID)));
        } else {
            ra[r] = __ldcg(reinterpret_cast<const float4*>(A0 + (m0 + row) * HID + k));
        }
        // B tile: weights (immutable inputs).
        if (PH == 2) {
            rb[r] = *reinterpret_cast<const float4*>(B0 + row * HID + k);
        } else {
            const int n = ((row >> 4) << 9) + j0 + (row & 15);
            if (PH == 0) {
                if (k < IN_DIM)
                    rb[r] = *reinterpret_cast<const float4*>(B0 + n * IN_DIM + k);
                else
                    rb[r] = *reinterpret_cast<const float4*>(B1 + n * HID + (k - IN_DIM));
            } else {
                if (k < HID)
                    rb[r] = *reinterpret_cast<const float4*>(B0 + n * HID + k);
                else
                    rb[r] = *reinterpret_cast<const float4*>(B1 + n * HID + (k - HID));
            }
        }
    }
}

template <int PH>
__device__ __forceinline__ void run_gemm(
    const float* __restrict__ A0, const float* __restrict__ A1,
    const float* __restrict__ B0, const float* __restrict__ B1,
    int m0, int j0, float* smem, float (&acc)[2][4][4]) {
    constexpr int KTOT = (PH == 0) ? (IN_DIM + HID) : ((PH == 1) ? (2 * HID) : HID);
    const int tid  = threadIdx.x;
    const int warp = tid >> 5, lane = tid & 31;
    const int grp  = lane >> 2, tig = lane & 3;
    const int wm0  = (warp >> 1) * 32, wn0 = (warp & 1) * 32;
    float* As = smem;             // [64][36] (pad 36 -> conflict-free frag loads)
    float* Bs = smem + 64 * 36;   // [64][36]

#pragma unroll
    for (int ma = 0; ma < 2; ma++)
#pragma unroll
        for (int na = 0; na < 4; na++)
#pragma unroll
            for (int i = 0; i < 4; i++) acc[ma][na][i] = 0.f;

    float4 ra[4], rb[4];
    fetchAB<PH>(0, m0, j0, A0, A1, B0, B1, ra, rb);

#pragma unroll 1
    for (int kb = 0; kb < KTOT; kb += 32) {
        __syncthreads();
#pragma unroll
        for (int r = 0; r < 4; r++) {
            const int item = tid + 128 * r;
            const int row  = item >> 3;
            const int c4   = 4 * (item & 7);
            float4 v = ra[r];
            v.x = rtf32(v.x); v.y = rtf32(v.y); v.z = rtf32(v.z); v.w = rtf32(v.w);
            *reinterpret_cast<float4*>(&As[row * 36 + c4]) = v;
            float4 w = rb[r];
            w.x = rtf32(w.x); w.y = rtf32(w.y); w.z = rtf32(w.z); w.w = rtf32(w.w);
            *reinterpret_cast<float4*>(&Bs[row * 36 + c4]) = w;
        }
        if (kb + 32 < KTOT) fetchAB<PH>(kb + 32, m0, j0, A0, A1, B0, B1, ra, rb);
        __syncthreads();
#pragma unroll
        for (int s = 0; s < 4; s++) {
            const int kk = 8 * s;
            uint32_t af[2][4], bf[4][2];
#pragma unroll
            for (int ma = 0; ma < 2; ma++) {
                const float* p = &As[(wm0 + 16 * ma + grp) * 36 + kk + tig];
                af[ma][0] = __float_as_uint(p[0]);
                af[ma][1] = __float_as_uint(p[8 * 36]);
                af[ma][2] = __float_as_uint(p[4]);
                af[ma][3] = __float_as_uint(p[8 * 36 + 4]);
            }
#pragma unroll
            for (int na = 0; na < 4; na++) {
                const float* p = &Bs[(wn0 + 8 * na + grp) * 36 + kk + tig];
                bf[na][0] = __float_as_uint(p[0]);
                bf[na][1] = __float_as_uint(p[4]);
            }
#pragma unroll
            for (int ma = 0; ma < 2; ma++)
#pragma unroll
                for (int na = 0; na < 4; na++) mma_tf32(acc[ma][na], af[ma], bf[na]);
        }
    }
}

// Fused LSTM-cell epilogue: stage gate tile in smem (aliases As/Bs), then each
// thread computes 8 (batch, hidden) cells and writes h (tf32-rounded) and c.
__device__ __forceinline__ void cell_epilogue(
    float (&acc)[2][4][4], float* smem, int m0, int j0,
    const float* __restrict__ bi, const float* __restrict__ bh,
    float* __restrict__ cbuf, float* __restrict__ hw) {
    float* gates = smem;  // [64][68]
    const int tid  = threadIdx.x;
    const int warp = tid >> 5, lane = tid & 31;
    const int grp  = lane >> 2, tig = lane & 3;
    const int wm0  = (warp >> 1) * 32, wn0 = (warp & 1) * 32;
    __syncthreads();  // all warps done reading As/Bs
#pragma unroll
    for (int ma = 0; ma < 2; ma++)
#pragma unroll
        for (int na = 0; na < 4; na++) {
            const int r0 = wm0 + 16 * ma + grp;
            const int c  = wn0 + 8 * na + 2 * tig;
            gates[r0 * 68 + c]           = acc[ma][na][0];
            gates[r0 * 68 + c + 1]       = acc[ma][na][1];
            gates[(r0 + 8) * 68 + c]     = acc[ma][na][2];
            gates[(r0 + 8) * 68 + c + 1] = acc[ma][na][3];
        }
    __syncthreads();
#pragma unroll
    for (int rep = 0; rep < 8; rep++) {
        const int it = tid + 128 * rep;
        const int m = it >> 4, jj = it & 15;
        const int b = m0 + m, j = j0 + jj;
        const float iv = gates[m * 68 + jj]      + bi[j]           + bh[j];
        const float fv = gates[m * 68 + 16 + jj] + bi[HID + j]     + bh[HID + j];
        const float gv = gates[m * 68 + 32 + jj] + bi[2 * HID + j] + bh[2 * HID + j];
        const float ov = gates[m * 68 + 48 + jj] + bi[3 * HID + j] + bh[3 * HID + j];
        const float c_old = cbuf[b * HID + j];
        const float cn = fmaf(sigf(fv), c_old, sigf(iv) * tanhf(gv));
        const float hn = sigf(ov) * tanhf(cn);
        cbuf[b * HID + j] = cn;
        hw[b * HID + j]   = rtf32(hn);
    }
}

__device__ __forceinline__ void linear_epilogue(
    float (&acc)[2][4][4], int m0, int tt,
    const float* __restrict__ blin, float* __restrict__ out) {
    const int tid  = threadIdx.x;
    const int warp = tid >> 5, lane = tid & 31;
    const int grp  = lane >> 2, tig = lane & 3;
    const int wm0  = (warp >> 1) * 32, wn0 = (warp & 1) * 32;
    const long row_stride = (long)T_STEPS * OUT_DIM;
#pragma unroll
    for (int ma = 0; ma < 2; ma++)
#pragma unroll
        for (int na = 0; na < 4; na++) {
            const int r = m0 + wm0 + 16 * ma + grp;
            const int c = wn0 + 8 * na + 2 * tig;
            float* o = out + (long)r * row_stride + tt * OUT_DIM + c;
            o[0] = acc[ma][na][0] + blin[c];
            o[1] = acc[ma][na][1] + blin[c + 1];
            float* o2 = o + 8 * row_stride;
            o2[0] = acc[ma][na][2] + blin[c];
            o2[1] = acc[ma][na][3] + blin[c + 1];
        }
}

__global__ void prep_kernel() {
    const int n = BATCH * HID;
    const int i = blockIdx.x * blockDim.x + threadIdx.x;
    if (i == 0) { g_count = 0; g_gen = 0; }
    for (int k = i; k < n; k += blockDim.x * gridDim.x) {
        g_h0[0][k] = 0.f; g_h0[1][k] = 0.f; g_c0[k] = 0.f;
        g_h1[0][k] = 0.f; g_h1[1][k] = 0.f; g_c1[k] = 0.f;
    }
}

__global__ void __launch_bounds__(128, 1) lstm_persistent(
    const float* __restrict__ x,
    const float* __restrict__ Wih0, const float* __restrict__ Whh0,
    const float* __restrict__ bih0, const float* __restrict__ bhh0,
    const float* __restrict__ Wih1, const float* __restrict__ Whh1,
    const float* __restrict__ bih1, const float* __restrict__ bhh1,
    const float* __restrict__ Wlin, const float* __restrict__ blin,
    float* __restrict__ out) {
    __shared__ __align__(16) float smem[2 * 64 * 36];
    const int bid = blockIdx.x;
    unsigned gen = 0;
    const int mi = bid >> 5, jn = bid & 31;  // valid for bid < 128
    const int m0g = mi * 64, j0 = jn * 16;
    float acc[2][4][4];

    for (int t = 0; t < T_STEPS; t++) {
        const int rp = t & 1, wp = rp ^ 1;
        if (bid < 128) {
            // Phase A: layer-0 gates + cell
            run_gemm<0>(x + (size_t)t * BATCH * IN_DIM, g_h0[rp], Wih0, Whh0,
                        m0g, j0, smem, acc);
            cell_epilogue(acc, smem, m0g, j0, bih0, bhh0, g_c0, g_h0[wp]);
        } else if (t > 0) {
            // Output linear for the previous step (runs concurrently w/ phase A)
            run_gemm<2>(g_h1[rp], nullptr, Wlin, nullptr,
                        (bid - 128) * 64, 0, smem, acc);
            linear_epilogue(acc, (bid - 128) * 64, t - 1, blin, out);
        }
        grid_sync(gen);
        if (bid < 128) {
            // Phase B: layer-1 gates + cell
            run_gemm<1>(g_h0[wp], g_h1[rp], Wih1, Whh1, m0g, j0, smem, acc);
            cell_epilogue(acc, smem, m0g, j0, bih1, bhh1, g_c1, g_h1[wp]);
        }
        grid_sync(gen);
    }
    // Final output linear for t = T-1 (h1 state lives in buffer parity T&1 == 0)
    if (bid >= 128) {
        run_gemm<2>(g_h1[0], nullptr, Wlin, nullptr,
                    (bid - 128) * 64, 0, smem, acc);
        linear_epilogue(acc, (bid - 128) * 64, T_STEPS - 1, blin, out);
    }
}

extern "C" void kernel_launch(void* const* d_in, const int* in_sizes, int n_in,
                              void* d_out, int out_size) {
    (void)in_sizes; (void)n_in; (void)out_size;
    const float* x    = (const float*)d_in[0];
    const float* Wih0 = (const float*)d_in[1];
    const float* Whh0 = (const float*)d_in[2];
    const float* bih0 = (const float*)d_in[3];
    const float* bhh0 = (const float*)d_in[4];
    const float* Wih1 = (const float*)d_in[5];
    const float* Whh1 = (const float*)d_in[6];
    const float* bih1 = (const float*)d_in[7];
    const float* bhh1 = (const float*)d_in[8];
    const float* Wlin = (const float*)d_in[9];
    const float* blin = (const float*)d_in[10];
    // d_in[11] = future (always 0) — ignored.
    float* out = (float*)d_out;

    prep_kernel<<<128, 256>>>();
    lstm_persistent<<<NCTA, 128>>>(x, Wih0, Whh0, bih0, bhh0,
                                   Wih1, Whh1, bih1, bhh1, Wlin, blin, out);
}